// round 7
// baseline (speedup 1.0000x reference)
#include <cuda_runtime.h>

// Problem constants
#define TT     64
#define CC     32
#define HDIM   24
#define BB     16384
#define FF     2048
#define HHEAD  48

// Gram kernel tiling
#define CHUNKS        32
#define ROWS_PER_CTA  (BB / CHUNKS)      // 512
#define TILE_R        64
#define TSTRIDE       66                 // stride-4 column reads -> conflict-free banks
#define NTILES        (ROWS_PER_CTA / TILE_R)  // 8
#define PSTRIDE       520                // per-group partial stride (16*32 padded)

// Scratch (device globals: no allocation allowed)
__device__ float g_G[TT * CC * CC];
__device__ float g_s[TT * CC];
__device__ float g_tails[TT];

// Packed fp32x2 FMA (Blackwell): d = a*b + d elementwise on two packed f32
__device__ __forceinline__ void ffma2(unsigned long long &d,
                                      unsigned long long a,
                                      unsigned long long b) {
    asm("fma.rn.f32x2 %0, %1, %2, %0;" : "+l"(d) : "l"(a), "l"(b));
}

__device__ __forceinline__ float2 unpack2(unsigned long long v) {
    float2 r;
    asm("mov.b64 {%0, %1}, %2;" : "=f"(r.x), "=f"(r.y) : "l"(v));
    return r;
}

__global__ void zero_kernel() {
    int i = blockIdx.x * blockDim.x + threadIdx.x;
    if (i < TT * CC * CC) g_G[i] = 0.f;
    if (i < TT * CC)      g_s[i] = 0.f;
    if (i < TT)           g_tails[i] = 0.f;
}

// Kernel 1: per-t Gram matrix G_t = X^T X and column sums s_t over a B-chunk.
// Grid: (TT, CHUNKS), 256 threads, 1 CTA/SM (register-heavy).
// Smem tile TRANSPOSED: xs[col][row], stride 66 floats.
// Compute: 16 groups of 16 threads; each thread owns an 8x8 tile of G at
// positions (i0+4ik, j0+4jk), i0,j0 in 0..3; f32x2 lanes paired along rows.
// Per 2-row step: 16 LDS.64 (128B) feed 64 FFMA2 (128 FMA) -> 1.0 FMA/byte.
__global__ void __launch_bounds__(256, 1)
gram_kernel(const float* __restrict__ x, const int* __restrict__ clusters) {
    // union: tile double-buffer (16.9KB) during mainloop, partials (33.3KB) after
    __shared__ __align__(16) char smem_raw[16 * PSTRIDE * 4];
    float (*xs)[CC * TSTRIDE] = (float (*)[CC * TSTRIDE])smem_raw;
    float* part = (float*)smem_raw;
    __shared__ int cidx[CC];

    const int t   = blockIdx.x;
    const int tid = threadIdx.x;
    if (tid < CC) cidx[tid] = clusters[t * CC + tid];
    __syncthreads();

    // ---- loader mapping: thread -> (col, 8 rows) ----
    const int lcol   = tid & 31;
    const int lrow0  = (tid >> 5) * 8;            // 8 rows per thread per tile
    const long rbase = (long)blockIdx.y * ROWS_PER_CTA;
    const float* __restrict__ xcol = x + cidx[lcol];

    // ---- compute mapping: 16 groups x (i0,j0) in 4x4 ----
    const int j0  = tid & 3;
    const int i0  = (tid >> 2) & 3;
    const int grp = tid >> 4;                      // 0..15, owns 4 rows of each tile

    unsigned long long acc[8][8];
#pragma unroll
    for (int a = 0; a < 8; a++)
#pragma unroll
        for (int b = 0; b < 8; b++) acc[a][b] = 0ull;

    float ld[8];
    float ssum = 0.f;

    // prefetch tile 0
#pragma unroll
    for (int rr = 0; rr < 8; rr++)
        ld[rr] = xcol[(rbase + lrow0 + rr) * FF];

    for (int tile = 0; tile < NTILES; tile++) {
        const int buf = tile & 1;
        // store prefetched rows (transposed) as four STS.64
        float2* dst = (float2*)&xs[buf][lcol * TSTRIDE + lrow0];
        dst[0] = make_float2(ld[0], ld[1]);
        dst[1] = make_float2(ld[2], ld[3]);
        dst[2] = make_float2(ld[4], ld[5]);
        dst[3] = make_float2(ld[6], ld[7]);
#pragma unroll
        for (int rr = 0; rr < 8; rr++) ssum += ld[rr];

        // prefetch next tile (hides DRAM latency behind this tile's compute)
        if (tile + 1 < NTILES) {
            const long rb = rbase + (long)(tile + 1) * TILE_R + lrow0;
#pragma unroll
            for (int rr = 0; rr < 8; rr++) ld[rr] = xcol[(rb + rr) * FF];
        }
        __syncthreads();   // one sync per tile: double buffer covers WAR hazard

        const float* __restrict__ xb = xs[buf];
#pragma unroll
        for (int step = 0; step < 2; step++) {
            const int r = grp * 4 + step * 2;      // this group's 2-row slab
            unsigned long long av[8], bv[8];
#pragma unroll
            for (int k = 0; k < 8; k++) {
                av[k] = *(const unsigned long long*)&xb[(i0 + 4 * k) * TSTRIDE + r];
                bv[k] = *(const unsigned long long*)&xb[(j0 + 4 * k) * TSTRIDE + r];
            }
#pragma unroll
            for (int ik = 0; ik < 8; ik++)
#pragma unroll
                for (int jk = 0; jk < 8; jk++)
                    ffma2(acc[ik][jk], av[ik], bv[jk]);
        }
    }
    __syncthreads();   // mainloop done; smem_raw is repurposed as `part`

    // reduce f32x2 pairs
    float facc[8][8];
#pragma unroll
    for (int ik = 0; ik < 8; ik++)
#pragma unroll
        for (int jk = 0; jk < 8; jk++) {
            float2 p = unpack2(acc[ik][jk]);
            facc[ik][jk] = p.x + p.y;
        }

    // CTA-level reduction over the 16 row-groups, two 16-row phases,
    // then one atomicAdd per Gram element per CTA.
    float* __restrict__ Gt = g_G + t * CC * CC;
    for (int half = 0; half < 2; half++) {
#pragma unroll
        for (int ik = 0; ik < 4; ik++)
#pragma unroll
            for (int jk = 0; jk < 8; jk++) {
                int i_loc = i0 + 4 * ik;           // 0..15
                int j     = j0 + 4 * jk;           // 0..31
                part[grp * PSTRIDE + i_loc * 32 + j] = facc[ik + 4 * half][jk];
            }
        __syncthreads();
        for (int o = tid; o < 512; o += 256) {
            float v = 0.f;
#pragma unroll
            for (int g = 0; g < 16; g++) v += part[g * PSTRIDE + o];
            atomicAdd(&Gt[half * 512 + o], v);
        }
        __syncthreads();
    }
    atomicAdd(&g_s[t * CC + lcol], ssum);
}

// Kernel 2: per-t finalize. A = M M^T - I, k = M hb + vb,
// SSR = sum_c (A^T G A)_cc + 2 (s A).k + B |k|^2 ; tails = 0.5*log(SSR/(B*C)).
__global__ void finalize_kernel(const float* __restrict__ Wt,
                                const float* __restrict__ hb,
                                const float* __restrict__ vb,
                                float* __restrict__ out) {
    const int t = blockIdx.x;
    const int c = threadIdx.x;  // 0..31

    __shared__ float Ms[CC * HDIM];
    __shared__ float Gs[CC * CC];
    __shared__ float ss[CC];

#pragma unroll
    for (int i = c; i < CC * HDIM; i += 32) Ms[i] = Wt[t * CC * HDIM + i];
#pragma unroll
    for (int i = c; i < CC * CC; i += 32)   Gs[i] = g_G[t * CC * CC + i];
    ss[c] = g_s[t * CC + c];
    __syncwarp();

    float Mc[HDIM];
#pragma unroll
    for (int h = 0; h < HDIM; h++) Mc[h] = Ms[c * HDIM + h];

    float a[CC];
#pragma unroll
    for (int i = 0; i < CC; i++) {
        float accv = 0.f;
#pragma unroll
        for (int h = 0; h < HDIM; h++) accv += Ms[i * HDIM + h] * Mc[h];
        a[i] = (i == c) ? (accv - 1.f) : accv;
    }

    float quad = 0.f, sA = 0.f;
#pragma unroll
    for (int i = 0; i < CC; i++) {
        float d = 0.f;
#pragma unroll
        for (int j = 0; j < CC; j++) d += Gs[i * CC + j] * a[j];
        quad += a[i] * d;
        sA   += ss[i] * a[i];
    }

    float kc = vb[t * CC + c];
#pragma unroll
    for (int h = 0; h < HDIM; h++) kc += hb[t * HDIM + h] * Mc[h];

    float contrib = quad + 2.f * kc * sA + (float)BB * kc * kc;
#pragma unroll
    for (int off = 16; off; off >>= 1)
        contrib += __shfl_xor_sync(0xffffffffu, contrib, off);

    if (c == 0) {
        float msr  = contrib * (1.f / (float)(BB * CC));
        float tail = 0.5f * logf(msr);
        g_tails[t] = tail;
        out[TT + t] = tail;              // tails occupy out[64..127]
    }
}

// Kernel 3: head, wide block to get load MLP (was 9.7us latency-bound).
#define HT 512
__global__ void head_kernel(const float* __restrict__ Wh,
                            const float* __restrict__ hbh,
                            const float* __restrict__ vbh,
                            float* __restrict__ out) {
    __shared__ float Whs[TT * HHEAD];   // 3072 floats
    __shared__ float tl[TT];
    __shared__ float hh[HHEAD];
    const int tid = threadIdx.x;

    for (int i = tid; i < TT * HHEAD; i += HT) Whs[i] = Wh[i];
    if (tid < TT) tl[tid] = g_tails[tid];
    __syncthreads();

    if (tid < HHEAD) {
        float accv = hbh[tid];
#pragma unroll 16
        for (int t = 0; t < TT; t++) accv += tl[t] * Whs[t * HHEAD + tid];
        hh[tid] = accv;
    }
    __syncthreads();

    if (tid < TT) {
        float accv = vbh[tid];
#pragma unroll 16
        for (int j = 0; j < HHEAD; j++) accv += hh[j] * Whs[tid * HHEAD + j];
        out[tid] = accv;                 // head_out occupies out[0..63]
    }
}

extern "C" void kernel_launch(void* const* d_in, const int* in_sizes, int n_in,
                              void* d_out, int out_size) {
    const float* x        = (const float*)d_in[0];
    const int*   clusters = (const int*)  d_in[1];
    const float* Wt       = (const float*)d_in[2];
    const float* hb       = (const float*)d_in[3];
    const float* vb       = (const float*)d_in[4];
    const float* Wh       = (const float*)d_in[5];
    const float* hbh      = (const float*)d_in[6];
    const float* vbh      = (const float*)d_in[7];
    float* out = (float*)d_out;

    zero_kernel<<<(TT * CC * CC + 255) / 256, 256>>>();
    gram_kernel<<<dim3(TT, CHUNKS), 256>>>(x, clusters);
    finalize_kernel<<<TT, 32>>>(Wt, hb, vb, out);
    head_kernel<<<1, HT>>>(Wh, hbh, vbh, out);
}

// round 8
// speedup vs baseline: 1.3753x; 1.3753x over previous
#include <cuda_runtime.h>

// Problem constants
#define TT     64
#define CC     32
#define HDIM   24
#define BB     16384
#define FF     2048
#define HHEAD  48

// Gram kernel tiling
#define CHUNKS        16
#define ROWS_PER_CTA  (BB / CHUNKS)      // 1024
#define TILE_R        64
#define SROW          34                 // row-major smem stride (floats); 34 mod 32 = 2
#define NTILES        (ROWS_PER_CTA / TILE_R)  // 16
#define PSTRIDE       520                // per-group partial stride (512 padded)

// Scratch (device globals: no allocation allowed)
__device__ float g_G[TT * CC * CC];
__device__ float g_s[TT * CC];
__device__ float g_tails[TT];
__device__ int   g_ctr;

// Packed fp32x2 FMA (Blackwell): d = a*b + d elementwise on two packed f32
__device__ __forceinline__ void ffma2(unsigned long long &d,
                                      unsigned long long a,
                                      unsigned long long b) {
    asm("fma.rn.f32x2 %0, %1, %2, %0;" : "+l"(d) : "l"(a), "l"(b));
}

__device__ __forceinline__ unsigned long long pack_dup(float a) {
    unsigned long long d;
    asm("mov.b64 %0, {%1, %1};" : "=l"(d) : "f"(a));
    return d;
}

__device__ __forceinline__ float2 unpack2(unsigned long long v) {
    float2 r;
    asm("mov.b64 {%0, %1}, %2;" : "=f"(r.x), "=f"(r.y) : "l"(v));
    return r;
}

__global__ void zero_kernel() {
    int i = blockIdx.x * blockDim.x + threadIdx.x;
    if (i < TT * CC * CC) g_G[i] = 0.f;
    if (i < TT * CC)      g_s[i] = 0.f;
    if (i == 0)           g_ctr  = 0;
}

// Kernel 1: per-t Gram matrix G_t = X^T X and column sums s_t over a B-chunk.
// Grid: (TT, CHUNKS), 256 threads, 2 CTAs/SM.
// Smem tile ROW-MAJOR: xs[row][col], stride 34 floats.
//   - fill: warp = one row, 32 consecutive cols -> STS.32 conflict-free
//   - b-loads: LDS.64 col-pairs {2j0+8m}, banks {2j0}+{0,8,16,24} disjoint
//   - a-loads: LDS.32 cols {i0+4k}, banks {0..3}+{0,8} disjoint
// Compute: 16 groups of 16 threads; thread owns 8 i-cols x 4 j-col-pairs.
// Per row per thread: 12 LDS (64B) + 8 dup-MOV feed 32 FFMA2 (64 FMA) -> 1.0 FMA/B.
__global__ void __launch_bounds__(256, 2)
gram_kernel(const float* __restrict__ x, const int* __restrict__ clusters) {
    // union: tile double-buffer (17.4KB) during mainloop, partials (33.3KB) after
    __shared__ __align__(16) char smem_raw[16 * PSTRIDE * 4];
    float* xs   = (float*)smem_raw;              // 2 * 64 * 34 floats
    float* part = (float*)smem_raw;
    __shared__ int cidx[CC];

    const int t   = blockIdx.x;
    const int tid = threadIdx.x;
    if (tid < CC) cidx[tid] = clusters[t * CC + tid];
    __syncthreads();

    // ---- loader mapping: thread -> (col, 8 rows) ----
    const int lcol   = tid & 31;
    const int lrow0  = (tid >> 5) * 8;            // 8 rows per thread per tile
    const long rbase = (long)blockIdx.y * ROWS_PER_CTA;
    const float* __restrict__ xcol = x + cidx[lcol];

    // ---- compute mapping: 16 groups x (i0 in 0..3, j0 in 0..3) ----
    const int j0  = tid & 3;
    const int i0  = (tid >> 2) & 3;
    const int grp = tid >> 4;                      // 0..15, owns rows grp*4..grp*4+3

    unsigned long long acc[8][4];
#pragma unroll
    for (int a = 0; a < 8; a++)
#pragma unroll
        for (int b = 0; b < 4; b++) acc[a][b] = 0ull;

    float ld[8];
    float ssum = 0.f;

    // prefetch tile 0
#pragma unroll
    for (int rr = 0; rr < 8; rr++)
        ld[rr] = xcol[(rbase + lrow0 + rr) * FF];

    for (int tile = 0; tile < NTILES; tile++) {
        float* xb = xs + (tile & 1) * (TILE_R * SROW);
        // row-major fill: STS.32, conflict-free (32 consecutive cols per warp)
#pragma unroll
        for (int rr = 0; rr < 8; rr++) {
            xb[(lrow0 + rr) * SROW + lcol] = ld[rr];
            ssum += ld[rr];
        }

        // prefetch next tile (hides DRAM latency behind this tile's compute)
        if (tile + 1 < NTILES) {
            const long rb = rbase + (long)(tile + 1) * TILE_R + lrow0;
#pragma unroll
            for (int rr = 0; rr < 8; rr++) ld[rr] = xcol[(rb + rr) * FF];
        }
        __syncthreads();   // one sync per tile: double buffer covers WAR hazard

#pragma unroll
        for (int step = 0; step < 4; step++) {
            const float* __restrict__ row = xb + (grp * 4 + step) * SROW;
            unsigned long long ap[8], bp[4];
#pragma unroll
            for (int m = 0; m < 4; m++)
                bp[m] = *(const unsigned long long*)&row[2 * j0 + 8 * m];
#pragma unroll
            for (int k = 0; k < 8; k++)
                ap[k] = pack_dup(row[i0 + 4 * k]);
#pragma unroll
            for (int k = 0; k < 8; k++)
#pragma unroll
                for (int m = 0; m < 4; m++)
                    ffma2(acc[k][m], ap[k], bp[m]);
        }
    }
    __syncthreads();   // mainloop done; smem_raw is repurposed as `part`

    // CTA-level reduction over the 16 row-groups, two 16-row halves,
    // then one atomicAdd per Gram element per CTA.
    // acc[k][m] holds (G[i0+4k][2j0+8m], G[i0+4k][2j0+8m+1]).
    float* __restrict__ Gt = g_G + t * CC * CC;
    for (int half = 0; half < 2; half++) {
#pragma unroll
        for (int kk = 0; kk < 4; kk++) {
            const int k     = kk + 4 * half;
            const int i_loc = i0 + 4 * kk;         // 0..15
#pragma unroll
            for (int m = 0; m < 4; m++) {
                float2 p = unpack2(acc[k][m]);
                const int j = 2 * j0 + 8 * m;
                part[grp * PSTRIDE + i_loc * 32 + j]     = p.x;
                part[grp * PSTRIDE + i_loc * 32 + j + 1] = p.y;
            }
        }
        __syncthreads();
        for (int o = tid; o < 512; o += 256) {
            float v = 0.f;
#pragma unroll
            for (int g = 0; g < 16; g++) v += part[g * PSTRIDE + o];
            atomicAdd(&Gt[half * 512 + o], v);
        }
        __syncthreads();
    }
    atomicAdd(&g_s[t * CC + lcol], ssum);
}

// Kernel 2: per-t finalize. A = M M^T - I, k = M hb + vb,
// SSR = sum_c (A^T G A)_cc + 2 (s A).k + B |k|^2 ; tails = 0.5*log(SSR/(B*C)).
// The LAST block (ticket) also computes the 64x48 head -> out[0..63].
__global__ void finalize_kernel(const float* __restrict__ Wt,
                                const float* __restrict__ hb,
                                const float* __restrict__ vb,
                                const float* __restrict__ Wh,
                                const float* __restrict__ hbh,
                                const float* __restrict__ vbh,
                                float* __restrict__ out) {
    const int t = blockIdx.x;
    const int c = threadIdx.x;  // 0..31

    __shared__ float Ms[CC * HDIM];
    __shared__ float Gs[CC * CC];
    __shared__ float ss[CC];

#pragma unroll
    for (int i = c; i < CC * HDIM; i += 32) Ms[i] = Wt[t * CC * HDIM + i];
#pragma unroll
    for (int i = c; i < CC * CC; i += 32)   Gs[i] = g_G[t * CC * CC + i];
    ss[c] = g_s[t * CC + c];
    __syncwarp();

    float Mc[HDIM];
#pragma unroll
    for (int h = 0; h < HDIM; h++) Mc[h] = Ms[c * HDIM + h];

    float a[CC];
#pragma unroll
    for (int i = 0; i < CC; i++) {
        float accv = 0.f;
#pragma unroll
        for (int h = 0; h < HDIM; h++) accv += Ms[i * HDIM + h] * Mc[h];
        a[i] = (i == c) ? (accv - 1.f) : accv;
    }

    float quad = 0.f, sA = 0.f;
#pragma unroll
    for (int i = 0; i < CC; i++) {
        float d = 0.f;
#pragma unroll
        for (int j = 0; j < CC; j++) d += Gs[i * CC + j] * a[j];
        quad += a[i] * d;
        sA   += ss[i] * a[i];
    }

    float kc = vb[t * CC + c];
#pragma unroll
    for (int h = 0; h < HDIM; h++) kc += hb[t * HDIM + h] * Mc[h];

    float contrib = quad + 2.f * kc * sA + (float)BB * kc * kc;
#pragma unroll
    for (int off = 16; off; off >>= 1)
        contrib += __shfl_xor_sync(0xffffffffu, contrib, off);

    if (c == 0) {
        float msr  = contrib * (1.f / (float)(BB * CC));
        float tail = 0.5f * logf(msr);
        g_tails[t] = tail;
        out[TT + t] = tail;              // tails occupy out[64..127]
    }

    // ---- last block computes the head (saves a kernel launch) ----
    __threadfence();
    int ticket = 0;
    if (c == 0) ticket = atomicAdd(&g_ctr, 1);
    ticket = __shfl_sync(0xffffffffu, ticket, 0);
    if (ticket != TT - 1) return;
    __threadfence();                      // acquire: see all g_tails stores

    __shared__ float tl[TT];
    __shared__ float hh[HHEAD];
    if (c == 0) g_ctr = 0;                // reset for next graph replay
#pragma unroll
    for (int i = c; i < TT; i += 32) tl[i] = g_tails[i];
    __syncwarp();
#pragma unroll
    for (int j = c; j < HHEAD; j += 32) {
        float accv = hbh[j];
#pragma unroll 8
        for (int u = 0; u < TT; u++) accv += tl[u] * Wh[u * HHEAD + j];
        hh[j] = accv;
    }
    __syncwarp();
#pragma unroll
    for (int i = c; i < TT; i += 32) {
        float accv = vbh[i];
#pragma unroll 8
        for (int j = 0; j < HHEAD; j++) accv += hh[j] * Wh[i * HHEAD + j];
        out[i] = accv;                    // head_out occupies out[0..63]
    }
}

extern "C" void kernel_launch(void* const* d_in, const int* in_sizes, int n_in,
                              void* d_out, int out_size) {
    const float* x        = (const float*)d_in[0];
    const int*   clusters = (const int*)  d_in[1];
    const float* Wt       = (const float*)d_in[2];
    const float* hb       = (const float*)d_in[3];
    const float* vb       = (const float*)d_in[4];
    const float* Wh       = (const float*)d_in[5];
    const float* hbh      = (const float*)d_in[6];
    const float* vbh      = (const float*)d_in[7];
    float* out = (float*)d_out;

    zero_kernel<<<(TT * CC * CC + 255) / 256, 256>>>();
    gram_kernel<<<dim3(TT, CHUNKS), 256>>>(x, clusters);
    finalize_kernel<<<TT, 32>>>(Wt, hb, vb, Wh, hbh, vbh, out);
}

// round 11
// speedup vs baseline: 2.5924x; 1.8850x over previous
#include <cuda_runtime.h>
#include <cuda_bf16.h>

// Problem constants
#define TT     64
#define CC     32
#define HDIM   24
#define BB     16384
#define FF     2048
#define HHEAD  48

// Gram tiling
#define CH     16                 // row chunks
#define RPC    (BB / CH)          // 1024 rows per CTA
#define TROWS  128                // rows per smem tile
#define NT     (RPC / TROWS)      // 8 tiles
#define SROWB  80                 // smem row stride bytes (40 bf16): ldmatrix conflict-free
#define TBYTES (TROWS * SROWB)    // 10240 per buffer
#define PRS    34                 // partial row stride (EVEN: float2-aligned)
#define PST    (16 * PRS)         // partial stride per warp (544)

// Scratch (device globals: no allocation allowed). All unique-writer: no zeroing.
__device__ float g_Gp[CH][TT][CC * CC];   // 4MB Gram partials
__device__ float g_sp[CH][TT * CC];       // col-sum partials
__device__ float g_tails[TT];
__device__ int   g_ctr;                   // static-zero; last block resets

// ---------------- helpers (sm_80-era only: compiles at plain sm_103) ----------------
__device__ __forceinline__ unsigned smem_u32(const void* p) {
    unsigned a;
    asm("{ .reg .u64 t; cvta.to.shared.u64 t, %1; cvt.u32.u64 %0, t; }" : "=r"(a) : "l"(p));
    return a;
}

__device__ __forceinline__ void ldsm4t(unsigned* r, unsigned addr) {
    asm volatile("ldmatrix.sync.aligned.m8n8.x4.trans.shared.b16 {%0,%1,%2,%3}, [%4];"
                 : "=r"(r[0]), "=r"(r[1]), "=r"(r[2]), "=r"(r[3]) : "r"(addr));
}

__device__ __forceinline__ void mma16816(float* d, const unsigned* a, const unsigned* b) {
    asm volatile(
        "mma.sync.aligned.m16n8k16.row.col.f32.bf16.bf16.f32 "
        "{%0,%1,%2,%3}, {%4,%5,%6,%7}, {%8,%9}, {%0,%1,%2,%3};"
        : "+f"(d[0]), "+f"(d[1]), "+f"(d[2]), "+f"(d[3])
        : "r"(a[0]), "r"(a[1]), "r"(a[2]), "r"(a[3]), "r"(b[0]), "r"(b[1]));
}

// ---------------- Kernel 1: fused gather+convert+Gram via mma.sync ----------------
// Grid (TT, CH), 256 threads = 8 warps.
// smem tile [k row][32 cols] bf16, stride 80B. Warp w consumes K rows w*16..+15
// per tile. A = tile^T (ldmatrix.trans), B = tile^T, D = 32x32 fp32 accum in regs.
__global__ void __launch_bounds__(256)
gram_kernel(const float* __restrict__ x, const int* __restrict__ clusters) {
    __shared__ __align__(16) unsigned char smt[2 * TBYTES];   // 20480B, reused as `part`
    __shared__ float4 sarr[32][8];                            // col-sum staging
    float* part = (float*)smt;                                // 8*PST floats = 17408B

    const int tid  = threadIdx.x;
    const int lane = tid & 31;
    const int w    = tid >> 5;
    const int q    = tid & 7;        // col quad (4 cols)
    const int rs   = tid >> 3;       // row slot (0..31)
    const int t    = blockIdx.x;
    const int chunk = blockIdx.y;

    const int cbase = clusters[t * CC];   // contiguous arange layout
    const long rbase = (long)chunk * RPC;
    const float* __restrict__ xp = x + (long)cbase + q * 4;

    // ldmatrix lane offsets (within a buffer); k slab base = w*16
    const int grp = lane >> 3, li = lane & 7;
    const unsigned offA = (unsigned)((w * 16 + (grp >> 1) * 8 + li) * SROWB + (grp & 1) * 16);
    const unsigned offB = (unsigned)((w * 16 + (grp & 1) * 8 + li) * SROWB + (grp >> 1) * 16);
    const unsigned smtu = smem_u32(smt);

    float d[2][4][4];
#pragma unroll
    for (int a = 0; a < 2; a++)
#pragma unroll
        for (int b = 0; b < 4; b++)
#pragma unroll
            for (int k = 0; k < 4; k++) d[a][b][k] = 0.f;

    float4 ssum = make_float4(0.f, 0.f, 0.f, 0.f);
    float4 pf[4];
#pragma unroll
    for (int j = 0; j < 4; j++)
        pf[j] = *(const float4*)&xp[(rbase + rs + 32 * j) * FF];

    for (int tile = 0; tile < NT; tile++) {
        unsigned char* bp = smt + (tile & 1) * TBYTES;
        const unsigned base = smtu + (tile & 1) * TBYTES;
        // store fp32 prefetch as bf16 pairs (STS.64), accumulate col sums
#pragma unroll
        for (int j = 0; j < 4; j++) {
            float4 v = pf[j];
            ssum.x += v.x; ssum.y += v.y; ssum.z += v.z; ssum.w += v.w;
            __nv_bfloat162 p0 = __floats2bfloat162_rn(v.x, v.y);
            __nv_bfloat162 p1 = __floats2bfloat162_rn(v.z, v.w);
            uint2 u;
            u.x = *(unsigned*)&p0;
            u.y = *(unsigned*)&p1;
            *(uint2*)(bp + (rs + 32 * j) * SROWB + q * 8) = u;
        }
        if (tile + 1 < NT) {
            const long rb = rbase + (long)(tile + 1) * TROWS;
#pragma unroll
            for (int j = 0; j < 4; j++)
                pf[j] = *(const float4*)&xp[(rb + rs + 32 * j) * FF];
        }
        __syncthreads();   // one sync/tile; double buffer covers WAR

        unsigned a0[4], a1[4], b0[4], b1[4];
        ldsm4t(a0, base + offA);        // A: i cols 0..15
        ldsm4t(a1, base + offA + 32);   // A: i cols 16..31
        ldsm4t(b0, base + offB);        // B: n 0..15
        ldsm4t(b1, base + offB + 32);   // B: n 16..31
        mma16816(d[0][0], a0, &b0[0]);
        mma16816(d[0][1], a0, &b0[2]);
        mma16816(d[0][2], a0, &b1[0]);
        mma16816(d[0][3], a0, &b1[2]);
        mma16816(d[1][0], a1, &b0[0]);
        mma16816(d[1][1], a1, &b0[2]);
        mma16816(d[1][2], a1, &b1[0]);
        mma16816(d[1][3], a1, &b1[2]);
    }
    __syncthreads();   // compute done: smt becomes `part`

    sarr[rs][q] = ssum;

    // D fragment (m16n8): c0,c1 -> (row lane/4, col nt*8+(lane%4)*2+{0,1});
    //                     c2,c3 -> row lane/4+8.
    const int r0 = lane >> 2;
    const int jc = (lane & 3) * 2;
    for (int h = 0; h < 2; h++) {      // m halves 0..15 / 16..31
#pragma unroll
        for (int nt = 0; nt < 4; nt++) {
            const int j0 = nt * 8 + jc;
            *(float2*)&part[w * PST + r0 * PRS + j0]       = make_float2(d[h][nt][0], d[h][nt][1]);
            *(float2*)&part[w * PST + (r0 + 8) * PRS + j0] = make_float2(d[h][nt][2], d[h][nt][3]);
        }
        __syncthreads();
        for (int e = tid; e < 512; e += 256) {
            float v = 0.f;
#pragma unroll
            for (int w2 = 0; w2 < 8; w2++)
                v += part[w2 * PST + (e >> 5) * PRS + (e & 31)];
            g_Gp[chunk][t][h * 512 + e] = v;     // unique writer
        }
        if (h == 0 && tid < 32) {
            float v = 0.f;
#pragma unroll
            for (int r2 = 0; r2 < 32; r2++)
                v += ((const float*)&sarr[r2][tid >> 2])[tid & 3];
            g_sp[chunk][t * CC + tid] = v;       // col index == tid
        }
        __syncthreads();
    }
}

// ---------------- Kernel 2: finalize (tails) + fused head on last block ----------------
#define FB 256
__global__ void __launch_bounds__(FB)
finalize_kernel(const float* __restrict__ Wt,  const float* __restrict__ hb,
                const float* __restrict__ vb,  const float* __restrict__ Wh,
                const float* __restrict__ hbh, const float* __restrict__ vbh,
                float* __restrict__ out) {
    const int t   = blockIdx.x;
    const int tid = threadIdx.x;
    const int c   = tid & 31;

    __shared__ float Gs[CC * CC];
    __shared__ float ss[CC];
    __shared__ float Ms[CC * HDIM];
    __shared__ float tl[TT];
    __shared__ float hh[HHEAD];

    for (int i = tid; i < CC * HDIM; i += FB) Ms[i] = Wt[t * CC * HDIM + i];
    for (int e = tid; e < CC * CC; e += FB) {
        float v = 0.f;
#pragma unroll
        for (int g = 0; g < CH; g++) v += g_Gp[g][t][e];
        Gs[e] = v;
    }
    if (tid < CC) {
        float v = 0.f;
#pragma unroll
        for (int g = 0; g < CH; g++) v += g_sp[g][t * CC + tid];
        ss[tid] = v;
    }
    __syncthreads();

    if (tid < 32) {
        float Mc[HDIM];
#pragma unroll
        for (int h = 0; h < HDIM; h++) Mc[h] = Ms[c * HDIM + h];

        float a[CC];
#pragma unroll
        for (int i = 0; i < CC; i++) {
            float accv = 0.f;
#pragma unroll
            for (int h = 0; h < HDIM; h++) accv += Ms[i * HDIM + h] * Mc[h];
            a[i] = (i == c) ? (accv - 1.f) : accv;
        }

        float quad = 0.f, sA = 0.f;
#pragma unroll
        for (int i = 0; i < CC; i++) {
            float dd = 0.f;
#pragma unroll
            for (int j = 0; j < CC; j++) dd += Gs[i * CC + j] * a[j];
            quad += a[i] * dd;
            sA   += ss[i] * a[i];
        }

        float kc = vb[t * CC + c];
#pragma unroll
        for (int h = 0; h < HDIM; h++) kc += hb[t * HDIM + h] * Mc[h];

        float contrib = quad + 2.f * kc * sA + (float)BB * kc * kc;
#pragma unroll
        for (int off = 16; off; off >>= 1)
            contrib += __shfl_xor_sync(0xffffffffu, contrib, off);

        if (c == 0) {
            float msr  = contrib * (1.f / (float)(BB * CC));
            float tail = 0.5f * logf(msr);
            g_tails[t] = tail;
            out[TT + t] = tail;                // tails occupy out[64..127]
        }

        // ---- last block computes the head ----
        __threadfence();
        int ticket = 0;
        if (c == 0) ticket = atomicAdd(&g_ctr, 1);
        ticket = __shfl_sync(0xffffffffu, ticket, 0);
        if (ticket == TT - 1) {
            __threadfence();                   // acquire: see all g_tails stores
            if (c == 0) g_ctr = 0;             // reset for next graph replay
#pragma unroll
            for (int i = c; i < TT; i += 32) tl[i] = g_tails[i];
            __syncwarp();
#pragma unroll
            for (int jj = c; jj < HHEAD; jj += 32) {
                float accv = hbh[jj];
#pragma unroll 8
                for (int u = 0; u < TT; u++) accv += tl[u] * Wh[u * HHEAD + jj];
                hh[jj] = accv;
            }
            __syncwarp();
#pragma unroll
            for (int i = c; i < TT; i += 32) {
                float accv = vbh[i];
#pragma unroll 8
                for (int jj = 0; jj < HHEAD; jj++) accv += hh[jj] * Wh[i * HHEAD + jj];
                out[i] = accv;                 // head_out occupies out[0..63]
            }
        }
    }
}

extern "C" void kernel_launch(void* const* d_in, const int* in_sizes, int n_in,
                              void* d_out, int out_size) {
    const float* x        = (const float*)d_in[0];
    const int*   clusters = (const int*)  d_in[1];
    const float* Wt       = (const float*)d_in[2];
    const float* hb       = (const float*)d_in[3];
    const float* vb       = (const float*)d_in[4];
    const float* Wh       = (const float*)d_in[5];
    const float* hbh      = (const float*)d_in[6];
    const float* vbh      = (const float*)d_in[7];
    float* out = (float*)d_out;

    gram_kernel<<<dim3(TT, CH), 256>>>(x, clusters);
    finalize_kernel<<<TT, FB>>>(Wt, hb, vb, Wh, hbh, vbh, out);
}